// round 3
// baseline (speedup 1.0000x reference)
#include <cuda_runtime.h>
#include <math.h>

#define NN 8192
#define INF_ 256
#define OUTF 128
#define ALPHA 0.2f

// Scratch (no allocations allowed in kernel_launch)
__device__ float g_Wh[NN * OUTF];   // 4 MB
__device__ float g_src[NN];
__device__ float g_dst[NN];

// ---------------------------------------------------------------------------
// Kernel A: Wh = h @ W   (8192x256 @ 256x128)
// grid 128, block 256. Each CTA: 64 rows x 128 cols. Thread: 4 rows x 8 cols.
// ---------------------------------------------------------------------------
__global__ __launch_bounds__(256) void wh_kernel(const float* __restrict__ h,
                                                 const float* __restrict__ W) {
    __shared__ float hs[64 * 68];    // 64 rows x 64 k, stride 68 (16B-aligned, bank-safe)
    __shared__ float Ws[64 * 128];   // 64 k x 128 cols

    const int tid = threadIdx.x;
    const int ty = tid >> 4;         // 0..15 -> rows ty*4..ty*4+3
    const int tx = tid & 15;         // 0..15 -> cols {tx*4..+3} and {64+tx*4..+3}
    const int rowbase = blockIdx.x * 64;

    float acc[4][8];
#pragma unroll
    for (int i = 0; i < 4; i++)
#pragma unroll
        for (int c = 0; c < 8; c++) acc[i][c] = 0.f;

    const float4* h4 = (const float4*)h;   // h row = 64 float4
    const float4* W4 = (const float4*)W;   // W row = 32 float4

    for (int kt = 0; kt < INF_; kt += 64) {
        __syncthreads();
        // stage h tile: 64 rows x 16 float4
#pragma unroll
        for (int s = 0; s < 4; s++) {
            int f4 = tid + s * 256;           // 0..1023
            int r = f4 >> 4, c4 = f4 & 15;
            float4 v = h4[(size_t)(rowbase + r) * 64 + (kt >> 2) + c4];
            *(float4*)&hs[r * 68 + c4 * 4] = v;
        }
        // stage W tile: 64 k x 32 float4 (linear)
#pragma unroll
        for (int s = 0; s < 8; s++) {
            int f4 = tid + s * 256;           // 0..2047
            ((float4*)Ws)[f4] = W4[kt * 32 + f4];
        }
        __syncthreads();

#pragma unroll 8
        for (int k = 0; k < 64; k++) {
            float hv[4];
#pragma unroll
            for (int i = 0; i < 4; i++) hv[i] = hs[(ty * 4 + i) * 68 + k];
            float4 w0 = *(const float4*)&Ws[k * 128 + tx * 4];
            float4 w1 = *(const float4*)&Ws[k * 128 + 64 + tx * 4];
#pragma unroll
            for (int i = 0; i < 4; i++) {
                acc[i][0] += hv[i] * w0.x; acc[i][1] += hv[i] * w0.y;
                acc[i][2] += hv[i] * w0.z; acc[i][3] += hv[i] * w0.w;
                acc[i][4] += hv[i] * w1.x; acc[i][5] += hv[i] * w1.y;
                acc[i][6] += hv[i] * w1.z; acc[i][7] += hv[i] * w1.w;
            }
        }
    }

#pragma unroll
    for (int i = 0; i < 4; i++) {
        int r = rowbase + ty * 4 + i;
        float4 o0 = make_float4(acc[i][0], acc[i][1], acc[i][2], acc[i][3]);
        float4 o1 = make_float4(acc[i][4], acc[i][5], acc[i][6], acc[i][7]);
        ((float4*)g_Wh)[(size_t)r * 32 + tx] = o0;
        ((float4*)g_Wh)[(size_t)r * 32 + 16 + tx] = o1;
    }
}

// ---------------------------------------------------------------------------
// Kernel B: src = Wh @ a1, dst = Wh @ a2.  4 threads per row.
// grid 128, block 256 (64 rows per block).
// ---------------------------------------------------------------------------
__global__ __launch_bounds__(256) void srcdst_kernel(const float* __restrict__ a) {
    const int tid = threadIdx.x;
    const int row = blockIdx.x * 64 + (tid >> 2);
    const int q = tid & 3;                       // quarter of the 128 cols
    const float4* wh4 = (const float4*)(g_Wh + (size_t)row * 128) + q * 8;
    const float4* a4 = (const float4*)a;
    float s1 = 0.f, s2 = 0.f;
#pragma unroll
    for (int t = 0; t < 8; t++) {
        float4 v = wh4[t];
        float4 b1 = a4[q * 8 + t];
        float4 b2 = a4[32 + q * 8 + t];
        s1 += v.x * b1.x + v.y * b1.y + v.z * b1.z + v.w * b1.w;
        s2 += v.x * b2.x + v.y * b2.y + v.z * b2.z + v.w * b2.w;
    }
    s1 += __shfl_xor_sync(0xffffffffu, s1, 1);
    s1 += __shfl_xor_sync(0xffffffffu, s1, 2);
    s2 += __shfl_xor_sync(0xffffffffu, s2, 1);
    s2 += __shfl_xor_sync(0xffffffffu, s2, 2);
    if (q == 0) { g_src[row] = s1; g_dst[row] = s2; }
}

// ---------------------------------------------------------------------------
// Kernel C: fused masked-softmax attention + aggregation + ELU.
// out[i,:] = elu( (sum_j adj_ij * exp(lrelu(src_i+dst_j)) * Wh[j,:]) / denom_i )
// No max-subtraction needed: e is bounded, exp() is safe in fp32, softmax is
// shift-invariant, so single streaming pass.
// grid 128 (64 rows/CTA), block 256. j tiled by 32.
// ---------------------------------------------------------------------------
__global__ __launch_bounds__(256) void attn_kernel(const int* __restrict__ adj,
                                                   float* __restrict__ out) {
    __shared__ float Whs[32 * 128];   // 16 KB: 32 j-rows x 128 cols
    __shared__ float ps[64 * 68];     // ~17 KB: p tile, row stride 68
    __shared__ float dtot[64];

    const int tid = threadIdx.x;
    const int ty = tid >> 4;          // MMA: rows ty*4..+3
    const int tx = tid & 15;          // MMA: cols {tx*4..} and {64+tx*4..}
    const int rowbase = blockIdx.x * 64;

    // p-phase roles: thread covers rows {pr, pr+32}, j quad pj..pj+3 (per tile)
    const int pr = tid >> 3;          // 0..31
    const int pj = (tid & 7) * 4;     // 0,4,...,28

    const float src0 = g_src[rowbase + pr];
    const float src1 = g_src[rowbase + pr + 32];
    const int* adjr0 = adj + (size_t)(rowbase + pr) * NN;
    const int* adjr1 = adj + (size_t)(rowbase + pr + 32) * NN;

    float dpart0 = 0.f, dpart1 = 0.f;
    float acc[4][8];
#pragma unroll
    for (int i = 0; i < 4; i++)
#pragma unroll
        for (int c = 0; c < 8; c++) acc[i][c] = 0.f;

    for (int jt = 0; jt < NN; jt += 32) {
        __syncthreads();   // previous tile fully consumed

        // stage Wh tile: 32 rows x 32 float4 = 1024 f4, 4 per thread (linear, coalesced)
#pragma unroll
        for (int s = 0; s < 4; s++) {
            int f4 = tid + s * 256;
            ((float4*)Whs)[f4] = ((const float4*)g_Wh)[(size_t)jt * 32 + f4];
        }

        // p tile
        float d0 = g_dst[jt + pj + 0];
        float d1 = g_dst[jt + pj + 1];
        float d2 = g_dst[jt + pj + 2];
        float d3 = g_dst[jt + pj + 3];
        int4 a0 = *(const int4*)(adjr0 + jt + pj);
        int4 a1v = *(const int4*)(adjr1 + jt + pj);

        {
            float t0 = src0 + d0, t1 = src0 + d1, t2 = src0 + d2, t3 = src0 + d3;
            t0 = t0 > 0.f ? t0 : ALPHA * t0;
            t1 = t1 > 0.f ? t1 : ALPHA * t1;
            t2 = t2 > 0.f ? t2 : ALPHA * t2;
            t3 = t3 > 0.f ? t3 : ALPHA * t3;
            float p0 = a0.x ? __expf(t0) : 0.f;
            float p1 = a0.y ? __expf(t1) : 0.f;
            float p2 = a0.z ? __expf(t2) : 0.f;
            float p3 = a0.w ? __expf(t3) : 0.f;
            ps[pr * 68 + pj + 0] = p0;
            ps[pr * 68 + pj + 1] = p1;
            ps[pr * 68 + pj + 2] = p2;
            ps[pr * 68 + pj + 3] = p3;
            dpart0 += (p0 + p1) + (p2 + p3);
        }
        {
            float t0 = src1 + d0, t1 = src1 + d1, t2 = src1 + d2, t3 = src1 + d3;
            t0 = t0 > 0.f ? t0 : ALPHA * t0;
            t1 = t1 > 0.f ? t1 : ALPHA * t1;
            t2 = t2 > 0.f ? t2 : ALPHA * t2;
            t3 = t3 > 0.f ? t3 : ALPHA * t3;
            float p0 = a1v.x ? __expf(t0) : 0.f;
            float p1 = a1v.y ? __expf(t1) : 0.f;
            float p2 = a1v.z ? __expf(t2) : 0.f;
            float p3 = a1v.w ? __expf(t3) : 0.f;
            ps[(pr + 32) * 68 + pj + 0] = p0;
            ps[(pr + 32) * 68 + pj + 1] = p1;
            ps[(pr + 32) * 68 + pj + 2] = p2;
            ps[(pr + 32) * 68 + pj + 3] = p3;
            dpart1 += (p0 + p1) + (p2 + p3);
        }
        __syncthreads();

        // accumulate: acc[i][:] += p[r][j] * Wh[j][:]
#pragma unroll 8
        for (int j = 0; j < 32; j++) {
            float4 w0 = *(const float4*)&Whs[j * 128 + tx * 4];
            float4 w1 = *(const float4*)&Whs[j * 128 + 64 + tx * 4];
#pragma unroll
            for (int i = 0; i < 4; i++) {
                float pv = ps[(ty * 4 + i) * 68 + j];
                acc[i][0] += pv * w0.x; acc[i][1] += pv * w0.y;
                acc[i][2] += pv * w0.z; acc[i][3] += pv * w0.w;
                acc[i][4] += pv * w1.x; acc[i][5] += pv * w1.y;
                acc[i][6] += pv * w1.z; acc[i][7] += pv * w1.w;
            }
        }
    }

    // denominator reduction (reuse ps)
    __syncthreads();
    ps[pr * 8 + (tid & 7)] = dpart0;
    ps[(pr + 32) * 8 + (tid & 7)] = dpart1;
    __syncthreads();
    if (tid < 64) {
        float s = 0.f;
#pragma unroll
        for (int k = 0; k < 8; k++) s += ps[tid * 8 + k];
        dtot[tid] = s;
    }
    __syncthreads();

    // epilogue: divide + ELU + store
#pragma unroll
    for (int i = 0; i < 4; i++) {
        int rl = ty * 4 + i;
        float rinv = 1.0f / dtot[rl];
        int r = rowbase + rl;
        float v[8];
#pragma unroll
        for (int c = 0; c < 8; c++) {
            float x = acc[i][c] * rinv;
            v[c] = x > 0.f ? x : expm1f(x);
        }
        float4 o0 = make_float4(v[0], v[1], v[2], v[3]);
        float4 o1 = make_float4(v[4], v[5], v[6], v[7]);
        ((float4*)out)[(size_t)r * 32 + tx] = o0;
        ((float4*)out)[(size_t)r * 32 + 16 + tx] = o1;
    }
}

// ---------------------------------------------------------------------------
extern "C" void kernel_launch(void* const* d_in, const int* in_sizes, int n_in,
                              void* d_out, int out_size) {
    const float* h = (const float*)d_in[0];     // (8192, 256) f32
    const int* adj = (const int*)d_in[1];       // (8192, 8192) i32
    const float* W = (const float*)d_in[2];     // (256, 128) f32
    const float* a = (const float*)d_in[3];     // (256,) f32
    float* out = (float*)d_out;                 // (8192, 128) f32

    wh_kernel<<<NN / 64, 256>>>(h, W);
    srcdst_kernel<<<NN / 64, 256>>>(a);
    attn_kernel<<<NN / 64, 256>>>(adj, out);
}

// round 5
// speedup vs baseline: 2.6861x; 2.6861x over previous
#include <cuda_runtime.h>
#include <stdint.h>
#include <math.h>

#define NN 8192
#define INF_ 256
#define OUTF 128

// ------------------------------ scratch ------------------------------------
__device__ float g_Wh[NN * OUTF];          // 4 MB  row-major [j][c]
__device__ float g_R[NN];                  // exp(0.8*src)
__device__ float g_Q[NN];                  // exp(0.8*dst)
__device__ float g_D5[NN];                 // exp(0.2*dst)
__device__ float g_pnum[2 * NN * OUTF];    // 8 MB  split-K partial numerators
__device__ float g_pden[2 * NN];           // split-K partial denominators

// ------------------------------ helpers ------------------------------------
__device__ __forceinline__ uint32_t tf32_cvt(float x) {
    uint32_t u;
    asm("cvt.rna.tf32.f32 %0, %1;" : "=r"(u) : "f"(x));
    return u;
}

// m16n8k8 tf32 MMA, fp32 accumulate (HMMA, valid on compute_103)
__device__ __forceinline__ void mma_tf32(float* d, const uint32_t* a, const uint32_t* b) {
    asm volatile(
        "mma.sync.aligned.m16n8k8.row.col.f32.tf32.tf32.f32 "
        "{%0,%1,%2,%3}, {%4,%5,%6,%7}, {%8,%9}, {%0,%1,%2,%3};"
        : "+f"(d[0]), "+f"(d[1]), "+f"(d[2]), "+f"(d[3])
        : "r"(a[0]), "r"(a[1]), "r"(a[2]), "r"(a[3]), "r"(b[0]), "r"(b[1]));
}

// ---------------------------------------------------------------------------
// Kernel A: Wh = h @ W   (8192x256 @ 256x128)
// ---------------------------------------------------------------------------
__global__ __launch_bounds__(256) void wh_kernel(const float* __restrict__ h,
                                                 const float* __restrict__ W) {
    __shared__ float hs[64 * 68];
    __shared__ float Ws[64 * 128];
    const int tid = threadIdx.x;
    const int ty = tid >> 4, tx = tid & 15;
    const int rowbase = blockIdx.x * 64;
    float acc[4][8];
#pragma unroll
    for (int i = 0; i < 4; i++)
#pragma unroll
        for (int c = 0; c < 8; c++) acc[i][c] = 0.f;
    const float4* h4 = (const float4*)h;
    const float4* W4 = (const float4*)W;
    for (int kt = 0; kt < INF_; kt += 64) {
        __syncthreads();
#pragma unroll
        for (int s = 0; s < 4; s++) {
            int f4 = tid + s * 256;
            int r = f4 >> 4, c4 = f4 & 15;
            float4 v = h4[(size_t)(rowbase + r) * 64 + (kt >> 2) + c4];
            *(float4*)&hs[r * 68 + c4 * 4] = v;
        }
#pragma unroll
        for (int s = 0; s < 8; s++) {
            int f4 = tid + s * 256;
            ((float4*)Ws)[f4] = W4[kt * 32 + f4];
        }
        __syncthreads();
#pragma unroll 8
        for (int k = 0; k < 64; k++) {
            float hv[4];
#pragma unroll
            for (int i = 0; i < 4; i++) hv[i] = hs[(ty * 4 + i) * 68 + k];
            float4 w0 = *(const float4*)&Ws[k * 128 + tx * 4];
            float4 w1 = *(const float4*)&Ws[k * 128 + 64 + tx * 4];
#pragma unroll
            for (int i = 0; i < 4; i++) {
                acc[i][0] += hv[i] * w0.x; acc[i][1] += hv[i] * w0.y;
                acc[i][2] += hv[i] * w0.z; acc[i][3] += hv[i] * w0.w;
                acc[i][4] += hv[i] * w1.x; acc[i][5] += hv[i] * w1.y;
                acc[i][6] += hv[i] * w1.z; acc[i][7] += hv[i] * w1.w;
            }
        }
    }
#pragma unroll
    for (int i = 0; i < 4; i++) {
        int r = rowbase + ty * 4 + i;
        ((float4*)g_Wh)[(size_t)r * 32 + tx] = make_float4(acc[i][0], acc[i][1], acc[i][2], acc[i][3]);
        ((float4*)g_Wh)[(size_t)r * 32 + 16 + tx] = make_float4(acc[i][4], acc[i][5], acc[i][6], acc[i][7]);
    }
}

// ---------------------------------------------------------------------------
// Kernel B: per-node R = exp(0.8*src), Q = exp(0.8*dst), D5 = exp(0.2*dst)
// ---------------------------------------------------------------------------
__global__ __launch_bounds__(256) void srcdst_kernel(const float* __restrict__ a) {
    const int tid = threadIdx.x;
    const int row = blockIdx.x * 64 + (tid >> 2);
    const int q = tid & 3;
    const float4* wh4 = (const float4*)(g_Wh + (size_t)row * 128) + q * 8;
    const float4* a4 = (const float4*)a;
    float s1 = 0.f, s2 = 0.f;
#pragma unroll
    for (int t = 0; t < 8; t++) {
        float4 v = wh4[t];
        float4 b1 = a4[q * 8 + t];
        float4 b2 = a4[32 + q * 8 + t];
        s1 += v.x * b1.x + v.y * b1.y + v.z * b1.z + v.w * b1.w;
        s2 += v.x * b2.x + v.y * b2.y + v.z * b2.z + v.w * b2.w;
    }
    s1 += __shfl_xor_sync(0xffffffffu, s1, 1);
    s1 += __shfl_xor_sync(0xffffffffu, s1, 2);
    s2 += __shfl_xor_sync(0xffffffffu, s2, 1);
    s2 += __shfl_xor_sync(0xffffffffu, s2, 2);
    if (q == 0) {
        g_R[row] = __expf(0.8f * s1);
        g_Q[row] = __expf(0.8f * s2);
        g_D5[row] = __expf(0.2f * s2);
    }
}

// ---------------------------------------------------------------------------
// Kernel C: fused masked-attention GEMM via mma.sync tf32, split-K by 2.
// grid = 128 (64 row-blocks x 2 K-halves), block = 256 (8 warps).
// P_ij = adj ? max(R_i*Q_j, 1) : 0 ; B[j][c] = D5_j * Wh[j][c] (tf32)
// num = P @ B (fp32 acc), den = sum_j P_ij * D5_j (scalar).
// ---------------------------------------------------------------------------
#define PST 36     // P smem row stride (floats): conflict-free A-frag loads
#define BST 132    // B smem row stride (floats): conflict-free B-frag loads
#define SM_P   0
#define SM_B   (128 * PST)                 // 4608
#define SM_Q   (SM_B + 32 * BST)           // 8832
#define SM_D5  (SM_Q + 4096)               // 12928
#define SM_DEN (SM_D5 + 4096)              // 17024
#define ATTN_SMEM ((SM_DEN + 1024) * 4)    // 72192 bytes

__global__ __launch_bounds__(256, 1) void attn_mma_kernel(const int* __restrict__ adj) {
    extern __shared__ float sm[];
    float* Ps = sm + SM_P;
    float* Bs = sm + SM_B;
    float* Qs = sm + SM_Q;
    float* D5s = sm + SM_D5;
    float* Dens = sm + SM_DEN;

    const int tid = threadIdx.x;
    const int lane = tid & 31, wid = tid >> 5;
    const int rb = blockIdx.x >> 1, kh = blockIdx.x & 1;
    const int row0 = rb * 128, k0 = kh * 4096;

    // stage Q, D5 for this K half
    for (int i = tid; i < 1024; i += 256) {
        ((float4*)Qs)[i] = ((const float4*)(g_Q + k0))[i];
        ((float4*)D5s)[i] = ((const float4*)(g_D5 + k0))[i];
    }

    // P-build roles
    const int r0 = tid >> 3;                 // 0..31
    const int jq = tid & 7;                  // j quad
    float Rr[4], den[4];
    const int4* adjp[4];
#pragma unroll
    for (int cc = 0; cc < 4; cc++) {
        Rr[cc] = g_R[row0 + r0 + 32 * cc];
        den[cc] = 0.f;
        adjp[cc] = (const int4*)(adj + (size_t)(row0 + r0 + 32 * cc) * NN + k0);
    }

    // MMA roles: warp grid 4(m) x 2(n); warp tile 32x64
    const int wm = wid >> 1, wn = wid & 1;
    const int gr = lane >> 2, tg = lane & 3;
    float acc[2][8][4];
#pragma unroll
    for (int mt = 0; mt < 2; mt++)
#pragma unroll
        for (int nt = 0; nt < 8; nt++)
#pragma unroll
            for (int i = 0; i < 4; i++) acc[mt][nt][i] = 0.f;

    __syncthreads();    // Q/D5 staged

    // prefetch tile 0
    int4 av[4];
    float4 bv[4];
#pragma unroll
    for (int cc = 0; cc < 4; cc++) av[cc] = adjp[cc][jq];
#pragma unroll
    for (int s2 = 0; s2 < 4; s2++) {
        int f4 = tid + s2 * 256;
        bv[s2] = ((const float4*)g_Wh)[(size_t)(k0 + (f4 >> 5)) * 32 + (f4 & 31)];
    }

    for (int s = 0; s < 128; s++) {
        const int jbase = s * 32;

        // ---- stage P (with tf32 cvt) + den ----
        const float4 qv = *(const float4*)(Qs + jbase + jq * 4);
        const float4 dv = *(const float4*)(D5s + jbase + jq * 4);
#pragma unroll
        for (int cc = 0; cc < 4; cc++) {
            const int row = r0 + 32 * cc;
            const float R = Rr[cc];
            const int4 a = av[cc];
            float p0 = a.x ? fmaxf(R * qv.x, 1.0f) : 0.0f;
            float p1 = a.y ? fmaxf(R * qv.y, 1.0f) : 0.0f;
            float p2 = a.z ? fmaxf(R * qv.z, 1.0f) : 0.0f;
            float p3 = a.w ? fmaxf(R * qv.w, 1.0f) : 0.0f;
            den[cc] += (p0 * dv.x + p1 * dv.y) + (p2 * dv.z + p3 * dv.w);
            uint4 u = make_uint4(tf32_cvt(p0), tf32_cvt(p1), tf32_cvt(p2), tf32_cvt(p3));
            *(uint4*)&Ps[row * PST + jq * 4] = u;
        }
        // ---- stage B = D5_j * Wh[j][:] (tf32) ----
#pragma unroll
        for (int s2 = 0; s2 < 4; s2++) {
            int f4 = tid + s2 * 256;
            int j = f4 >> 5, c4 = (f4 & 31) * 4;
            float d5 = D5s[jbase + j];
            float4 v = bv[s2];
            uint4 u = make_uint4(tf32_cvt(v.x * d5), tf32_cvt(v.y * d5),
                                 tf32_cvt(v.z * d5), tf32_cvt(v.w * d5));
            *(uint4*)&Bs[j * BST + c4] = u;
        }
        __syncthreads();

        // ---- prefetch next tile (LDG latency hidden by MMA phase) ----
        if (s + 1 < 128) {
#pragma unroll
            for (int cc = 0; cc < 4; cc++) av[cc] = adjp[cc][(s + 1) * 8 + jq];
#pragma unroll
            for (int s2 = 0; s2 < 4; s2++) {
                int f4 = tid + s2 * 256;
                bv[s2] = ((const float4*)g_Wh)[(size_t)(k0 + jbase + 32 + (f4 >> 5)) * 32 + (f4 & 31)];
            }
        }

        // ---- MMA phase: K=32 in 4 ksteps of 8 ----
#pragma unroll
        for (int k = 0; k < 4; k++) {
            const int kk = k * 8;
            uint32_t afr[2][4];
#pragma unroll
            for (int mt = 0; mt < 2; mt++) {
                const int ra = wm * 32 + mt * 16;
                afr[mt][0] = *(const uint32_t*)&Ps[(ra + gr) * PST + kk + tg];
                afr[mt][1] = *(const uint32_t*)&Ps[(ra + gr + 8) * PST + kk + tg];
                afr[mt][2] = *(const uint32_t*)&Ps[(ra + gr) * PST + kk + tg + 4];
                afr[mt][3] = *(const uint32_t*)&Ps[(ra + gr + 8) * PST + kk + tg + 4];
            }
#pragma unroll
            for (int nt = 0; nt < 8; nt++) {
                uint32_t bfr[2];
                const int col = wn * 64 + nt * 8 + gr;
                bfr[0] = *(const uint32_t*)&Bs[(kk + tg) * BST + col];
                bfr[1] = *(const uint32_t*)&Bs[(kk + tg + 4) * BST + col];
                mma_tf32(acc[0][nt], afr[0], bfr);
                mma_tf32(acc[1][nt], afr[1], bfr);
            }
        }
        __syncthreads();
    }

    // ---- denominator reduce ----
#pragma unroll
    for (int cc = 0; cc < 4; cc++) Dens[(r0 + 32 * cc) * 8 + jq] = den[cc];
    __syncthreads();
    if (tid < 128) {
        const float* dr = Dens + tid * 8;
        float sden = 0.f;
#pragma unroll
        for (int k = 0; k < 8; k++) sden += dr[k];
        g_pden[kh * NN + row0 + tid] = sden;
    }

    // ---- numerator writeback ----
    const size_t base = (size_t)kh * NN + row0;
#pragma unroll
    for (int mt = 0; mt < 2; mt++) {
        const int r_lo = wm * 32 + mt * 16 + gr;
#pragma unroll
        for (int nt = 0; nt < 8; nt++) {
            const int col = wn * 64 + nt * 8 + 2 * tg;
            float2 v0 = make_float2(acc[mt][nt][0], acc[mt][nt][1]);
            float2 v1 = make_float2(acc[mt][nt][2], acc[mt][nt][3]);
            *(float2*)&g_pnum[(base + r_lo) * 128 + col] = v0;
            *(float2*)&g_pnum[(base + r_lo + 8) * 128 + col] = v1;
        }
    }
}

// ---------------------------------------------------------------------------
// Kernel D: finalize  out = elu((n0+n1)/(d0+d1))
// ---------------------------------------------------------------------------
__global__ __launch_bounds__(256) void finalize_kernel(float* __restrict__ out) {
    const int idx = blockIdx.x * 256 + threadIdx.x;
    const int row = idx >> 5, c4 = idx & 31;
    float4 n0 = ((const float4*)g_pnum)[(size_t)row * 32 + c4];
    float4 n1 = ((const float4*)g_pnum)[(size_t)(NN + row) * 32 + c4];
    const float rinv = 1.0f / (g_pden[row] + g_pden[NN + row]);
    float4 o;
    float x;
    x = (n0.x + n1.x) * rinv; o.x = x > 0.f ? x : expm1f(x);
    x = (n0.y + n1.y) * rinv; o.y = x > 0.f ? x : expm1f(x);
    x = (n0.z + n1.z) * rinv; o.z = x > 0.f ? x : expm1f(x);
    x = (n0.w + n1.w) * rinv; o.w = x > 0.f ? x : expm1f(x);
    ((float4*)out)[(size_t)row * 32 + c4] = o;
}

// ---------------------------------------------------------------------------
extern "C" void kernel_launch(void* const* d_in, const int* in_sizes, int n_in,
                              void* d_out, int out_size) {
    const float* h = (const float*)d_in[0];
    const int* adj = (const int*)d_in[1];
    const float* W = (const float*)d_in[2];
    const float* a = (const float*)d_in[3];
    float* out = (float*)d_out;

    cudaFuncSetAttribute(attn_mma_kernel, cudaFuncAttributeMaxDynamicSharedMemorySize,
                         ATTN_SMEM);

    wh_kernel<<<NN / 64, 256>>>(h, W);
    srcdst_kernel<<<NN / 64, 256>>>(a);
    attn_mma_kernel<<<128, 256, ATTN_SMEM>>>(adj);
    finalize_kernel<<<1024, 256>>>(out);
}

// round 10
// speedup vs baseline: 4.2305x; 1.5750x over previous
#include <cuda_runtime.h>
#include <cuda_fp16.h>
#include <stdint.h>
#include <math.h>

#define NN 8192
#define INF_ 256
#define OUTF 128

// ------------------------------ scratch ------------------------------------
__device__ float g_Wh[NN * OUTF];          // 4 MB  row-major [j][c]
__device__ float g_R[NN];                  // exp(0.8*src)
__device__ float g_Q[NN];                  // exp(0.8*dst)
__device__ float g_D5[NN];                 // exp(0.2*dst)
__device__ float g_pnum[2 * NN * OUTF];    // 8 MB  split-K partial numerators
__device__ float g_pden[2 * NN];           // split-K partial denominators

// ------------------------------ helpers ------------------------------------
__device__ __forceinline__ uint32_t smem_u32(const void* p) {
    return (uint32_t)__cvta_generic_to_shared(p);
}
__device__ __forceinline__ void ldsm_x4(uint32_t* r, uint32_t addr) {
    asm volatile("ldmatrix.sync.aligned.m8n8.x4.shared.b16 {%0,%1,%2,%3}, [%4];"
        : "=r"(r[0]), "=r"(r[1]), "=r"(r[2]), "=r"(r[3]) : "r"(addr));
}
__device__ __forceinline__ void ldsm_x4_t(uint32_t* r, uint32_t addr) {
    asm volatile("ldmatrix.sync.aligned.m8n8.x4.trans.shared.b16 {%0,%1,%2,%3}, [%4];"
        : "=r"(r[0]), "=r"(r[1]), "=r"(r[2]), "=r"(r[3]) : "r"(addr));
}
// m16n8k16 f16 MMA, fp32 accumulate
__device__ __forceinline__ void mma_f16(float* d, const uint32_t* a, const uint32_t* b) {
    asm volatile(
        "mma.sync.aligned.m16n8k16.row.col.f32.f16.f16.f32 "
        "{%0,%1,%2,%3}, {%4,%5,%6,%7}, {%8,%9}, {%0,%1,%2,%3};"
        : "+f"(d[0]), "+f"(d[1]), "+f"(d[2]), "+f"(d[3])
        : "r"(a[0]), "r"(a[1]), "r"(a[2]), "r"(a[3]), "r"(b[0]), "r"(b[1]));
}
__device__ __forceinline__ uint32_t pack_h2(float lo, float hi) {
    __half2 h = __float22half2_rn(make_float2(lo, hi));
    return *(uint32_t*)&h;
}

// ---------------------------------------------------------------------------
// Kernel A: Wh = h @ W   (8192x256 @ 256x128), fp32
// ---------------------------------------------------------------------------
__global__ __launch_bounds__(256) void wh_kernel(const float* __restrict__ h,
                                                 const float* __restrict__ W) {
    __shared__ float hs[64 * 68];
    __shared__ float Ws[64 * 128];
    const int tid = threadIdx.x;
    const int ty = tid >> 4, tx = tid & 15;
    const int rowbase = blockIdx.x * 64;
    float acc[4][8];
#pragma unroll
    for (int i = 0; i < 4; i++)
#pragma unroll
        for (int c = 0; c < 8; c++) acc[i][c] = 0.f;
    const float4* h4 = (const float4*)h;
    const float4* W4 = (const float4*)W;
    for (int kt = 0; kt < INF_; kt += 64) {
        __syncthreads();
#pragma unroll
        for (int s = 0; s < 4; s++) {
            int f4 = tid + s * 256;
            int r = f4 >> 4, c4 = f4 & 15;
            float4 v = h4[(size_t)(rowbase + r) * 64 + (kt >> 2) + c4];
            *(float4*)&hs[r * 68 + c4 * 4] = v;
        }
#pragma unroll
        for (int s = 0; s < 8; s++) {
            int f4 = tid + s * 256;
            ((float4*)Ws)[f4] = W4[kt * 32 + f4];
        }
        __syncthreads();
#pragma unroll 8
        for (int k = 0; k < 64; k++) {
            float hv[4];
#pragma unroll
            for (int i = 0; i < 4; i++) hv[i] = hs[(ty * 4 + i) * 68 + k];
            float4 w0 = *(const float4*)&Ws[k * 128 + tx * 4];
            float4 w1 = *(const float4*)&Ws[k * 128 + 64 + tx * 4];
#pragma unroll
            for (int i = 0; i < 4; i++) {
                acc[i][0] += hv[i] * w0.x; acc[i][1] += hv[i] * w0.y;
                acc[i][2] += hv[i] * w0.z; acc[i][3] += hv[i] * w0.w;
                acc[i][4] += hv[i] * w1.x; acc[i][5] += hv[i] * w1.y;
                acc[i][6] += hv[i] * w1.z; acc[i][7] += hv[i] * w1.w;
            }
        }
    }
#pragma unroll
    for (int i = 0; i < 4; i++) {
        int r = rowbase + ty * 4 + i;
        ((float4*)g_Wh)[(size_t)r * 32 + tx] = make_float4(acc[i][0], acc[i][1], acc[i][2], acc[i][3]);
        ((float4*)g_Wh)[(size_t)r * 32 + 16 + tx] = make_float4(acc[i][4], acc[i][5], acc[i][6], acc[i][7]);
    }
}

// ---------------------------------------------------------------------------
// Kernel B: per-node R = exp(0.8*src), Q = exp(0.8*dst), D5 = exp(0.2*dst)
// ---------------------------------------------------------------------------
__global__ __launch_bounds__(256) void srcdst_kernel(const float* __restrict__ a) {
    const int tid = threadIdx.x;
    const int row = blockIdx.x * 64 + (tid >> 2);
    const int q = tid & 3;
    const float4* wh4 = (const float4*)(g_Wh + (size_t)row * 128) + q * 8;
    const float4* a4 = (const float4*)a;
    float s1 = 0.f, s2 = 0.f;
#pragma unroll
    for (int t = 0; t < 8; t++) {
        float4 v = wh4[t];
        float4 b1 = a4[q * 8 + t];
        float4 b2 = a4[32 + q * 8 + t];
        s1 += v.x * b1.x + v.y * b1.y + v.z * b1.z + v.w * b1.w;
        s2 += v.x * b2.x + v.y * b2.y + v.z * b2.z + v.w * b2.w;
    }
    s1 += __shfl_xor_sync(0xffffffffu, s1, 1);
    s1 += __shfl_xor_sync(0xffffffffu, s1, 2);
    s2 += __shfl_xor_sync(0xffffffffu, s2, 1);
    s2 += __shfl_xor_sync(0xffffffffu, s2, 2);
    if (q == 0) {
        g_R[row] = __expf(0.8f * s1);
        g_Q[row] = __expf(0.8f * s2);
        g_D5[row] = __expf(0.2f * s2);
    }
}

// ---------------------------------------------------------------------------
// Kernel C: fused masked-attention GEMM via f16 m16n8k16 + ldmatrix.
// grid = 128 (64 row-blocks x 2 K-halves), block = 256 (8 warps = 4m x 2n).
// CTA tile: 128 rows x 128 cols, j-tile = 64.
// P_ij = adj ? max(R_i*Q_j, 1) : 0 (f16) ; B[j][c] = D5_j*Wh[j][c] (f16)
// num = P @ B (fp32 acc), den = sum_j P_ij*D5_j (fp32 scalar).
// ---------------------------------------------------------------------------
#define PST 72      // P smem row stride in halves (144 B) -> conflict-free
#define BST 136     // B smem row stride in halves (272 B) -> conflict-free

__global__ __launch_bounds__(256, 1) void attn_mma_kernel(const int* __restrict__ adj) {
    __shared__ __half Ps[128 * PST];    // 18432 B
    __shared__ __half Bs[64 * BST];     // 17408 B
    __shared__ float Dens[128 * 8];     //  4096 B

    const int tid = threadIdx.x;
    const int lane = tid & 31, wid = tid >> 5;
    const int rb = blockIdx.x >> 1, kh = blockIdx.x & 1;
    const int row0 = rb * 128, k0 = kh * 4096;

    // ---- P-build roles: thread covers rows {r0+32cc} x j in [jq*8, jq*8+8) ----
    const int r0 = tid >> 3;            // 0..31
    const int jq = tid & 7;             // 0..7
    float Rr[4], den[4];
    const int4* adjp[4];
#pragma unroll
    for (int cc = 0; cc < 4; cc++) {
        Rr[cc] = g_R[row0 + r0 + 32 * cc];
        den[cc] = 0.f;
        adjp[cc] = (const int4*)(adj + (size_t)(row0 + r0 + 32 * cc) * NN + k0) + jq * 2;
    }
    // B-build roles: 8 float4 per thread per tile; j = (tid>>5) + 8*s2, c4 = tid&31
    const int bj = tid >> 5, bc4 = tid & 31;

    // ---- MMA roles ----
    const int wm = wid >> 1, wn = wid & 1;
    const int gr = lane >> 2, tg = lane & 3;
    float acc[2][8][4];
#pragma unroll
    for (int mt = 0; mt < 2; mt++)
#pragma unroll
        for (int nt = 0; nt < 8; nt++)
#pragma unroll
            for (int i = 0; i < 4; i++) acc[mt][nt][i] = 0.f;

    // ldmatrix base addresses (lane-dependent parts precomputed)
    const uint32_t ps_base = smem_u32(Ps);
    const uint32_t bs_base = smem_u32(Bs);
    // A: row = wm*32 + mt*16 + (lane&15), col = kk + (lane>>4)*8
    const uint32_t a_lane_off = (uint32_t)((wm * 32 + (lane & 15)) * PST + (lane >> 4) * 8) * 2;
    // B: row = kk + (lane&15), col = wn*64 + pair*16 + (lane>>4)*8
    const uint32_t b_lane_off = (uint32_t)((lane & 15) * BST + wn * 64 + (lane >> 4) * 8) * 2;

    // ---- prefetch tile 0 ----
    int4 av[4][2];
    float4 bv[8];
#pragma unroll
    for (int cc = 0; cc < 4; cc++) {
        av[cc][0] = adjp[cc][0];
        av[cc][1] = adjp[cc][1];
    }
#pragma unroll
    for (int s2 = 0; s2 < 8; s2++)
        bv[s2] = ((const float4*)g_Wh)[(size_t)(k0 + bj + 8 * s2) * 32 + bc4];

    for (int s = 0; s < 64; s++) {
        const int jbase = s * 64;

        // ---- stage P (f16) + den ----
        const float4 qv0 = __ldg((const float4*)(g_Q + k0 + jbase + jq * 8));
        const float4 qv1 = __ldg((const float4*)(g_Q + k0 + jbase + jq * 8 + 4));
        const float4 dv0 = __ldg((const float4*)(g_D5 + k0 + jbase + jq * 8));
        const float4 dv1 = __ldg((const float4*)(g_D5 + k0 + jbase + jq * 8 + 4));
#pragma unroll
        for (int cc = 0; cc < 4; cc++) {
            const int row = r0 + 32 * cc;
            const float R = Rr[cc];
            const int4 a0 = av[cc][0], a1 = av[cc][1];
            float p0 = a0.x ? fmaxf(R * qv0.x, 1.0f) : 0.0f;
            float p1 = a0.y ? fmaxf(R * qv0.y, 1.0f) : 0.0f;
            float p2 = a0.z ? fmaxf(R * qv0.z, 1.0f) : 0.0f;
            float p3 = a0.w ? fmaxf(R * qv0.w, 1.0f) : 0.0f;
            float p4 = a1.x ? fmaxf(R * qv1.x, 1.0f) : 0.0f;
            float p5 = a1.y ? fmaxf(R * qv1.y, 1.0f) : 0.0f;
            float p6 = a1.z ? fmaxf(R * qv1.z, 1.0f) : 0.0f;
            float p7 = a1.w ? fmaxf(R * qv1.w, 1.0f) : 0.0f;
            den[cc] += ((p0 * dv0.x + p1 * dv0.y) + (p2 * dv0.z + p3 * dv0.w)) +
                       ((p4 * dv1.x + p5 * dv1.y) + (p6 * dv1.z + p7 * dv1.w));
            uint4 u = make_uint4(pack_h2(p0, p1), pack_h2(p2, p3),
                                 pack_h2(p4, p5), pack_h2(p6, p7));
            *(uint4*)&Ps[row * PST + jq * 8] = u;
        }
        // ---- stage B (f16) ----
#pragma unroll
        for (int s2 = 0; s2 < 8; s2++) {
            const int j = bj + 8 * s2;
            const float d5 = __ldg(g_D5 + k0 + jbase + j);
            float4 v = bv[s2];
            uint2 u = make_uint2(pack_h2(v.x * d5, v.y * d5), pack_h2(v.z * d5, v.w * d5));
            *(uint2*)&Bs[j * BST + bc4 * 4] = u;
        }
        __syncthreads();

        // ---- prefetch next tile ----
        if (s + 1 < 64) {
#pragma unroll
            for (int cc = 0; cc < 4; cc++) {
                av[cc][0] = adjp[cc][(s + 1) * 16];
                av[cc][1] = adjp[cc][(s + 1) * 16 + 1];
            }
#pragma unroll
            for (int s2 = 0; s2 < 8; s2++)
                bv[s2] = ((const float4*)g_Wh)[(size_t)(k0 + jbase + 64 + bj + 8 * s2) * 32 + bc4];
        }

        // ---- MMA: K=64 in 4 ksteps of 16 ----
#pragma unroll
        for (int k = 0; k < 4; k++) {
            const int kk = k * 16;
            uint32_t afr[2][4];
            ldsm_x4(afr[0], ps_base + a_lane_off + kk * 2);
            ldsm_x4(afr[1], ps_base + a_lane_off + (16 * PST + kk) * 2);
            uint32_t bfr[4][4];
#pragma unroll
            for (int pr = 0; pr < 4; pr++)
                ldsm_x4_t(bfr[pr], bs_base + b_lane_off + (kk * BST + pr * 16) * 2);
#pragma unroll
            for (int pr = 0; pr < 4; pr++) {
                mma_f16(acc[0][pr * 2], afr[0], &bfr[pr][0]);
                mma_f16(acc[1][pr * 2], afr[1], &bfr[pr][0]);
                mma_f16(acc[0][pr * 2 + 1], afr[0], &bfr[pr][2]);
                mma_f16(acc[1][pr * 2 + 1], afr[1], &bfr[pr][2]);
            }
        }
        __syncthreads();
    }

    // ---- denominator reduce ----
#pragma unroll
    for (int cc = 0; cc < 4; cc++) Dens[(r0 + 32 * cc) * 8 + jq] = den[cc];
    __syncthreads();
    if (tid < 128) {
        const float* dr = Dens + tid * 8;
        float sden = 0.f;
#pragma unroll
        for (int k = 0; k < 8; k++) sden += dr[k];
        g_pden[kh * NN + row0 + tid] = sden;
    }

    // ---- numerator writeback ----
    const size_t base = (size_t)kh * NN + row0;
#pragma unroll
    for (int mt = 0; mt < 2; mt++) {
        const int r_lo = wm * 32 + mt * 16 + gr;
#pragma unroll
        for (int nt = 0; nt < 8; nt++) {
            const int col = wn * 64 + nt * 8 + 2 * tg;
            *(float2*)&g_pnum[(base + r_lo) * 128 + col] = make_float2(acc[mt][nt][0], acc[mt][nt][1]);
            *(float2*)&g_pnum[(base + r_lo + 8) * 128 + col] = make_float2(acc[mt][nt][2], acc[mt][nt][3]);
        }
    }
}

// ---------------------------------------------------------------------------
// Kernel D: finalize  out = elu((n0+n1)/(d0+d1))
// ---------------------------------------------------------------------------
__global__ __launch_bounds__(256) void finalize_kernel(float* __restrict__ out) {
    const int idx = blockIdx.x * 256 + threadIdx.x;
    const int row = idx >> 5, c4 = idx & 31;
    float4 n0 = ((const float4*)g_pnum)[(size_t)row * 32 + c4];
    float4 n1 = ((const float4*)g_pnum)[(size_t)(NN + row) * 32 + c4];
    const float rinv = 1.0f / (g_pden[row] + g_pden[NN + row]);
    float4 o;
    float x;
    x = (n0.x + n1.x) * rinv; o.x = x > 0.f ? x : expm1f(x);
    x = (n0.y + n1.y) * rinv; o.y = x > 0.f ? x : expm1f(x);
    x = (n0.z + n1.z) * rinv; o.z = x > 0.f ? x : expm1f(x);
    x = (n0.w + n1.w) * rinv; o.w = x > 0.f ? x : expm1f(x);
    ((float4*)out)[(size_t)row * 32 + c4] = o;
}

// ---------------------------------------------------------------------------
extern "C" void kernel_launch(void* const* d_in, const int* in_sizes, int n_in,
                              void* d_out, int out_size) {
    const float* h = (const float*)d_in[0];
    const int* adj = (const int*)d_in[1];
    const float* W = (const float*)d_in[2];
    const float* a = (const float*)d_in[3];
    float* out = (float*)d_out;

    wh_kernel<<<NN / 64, 256>>>(h, W);
    srcdst_kernel<<<NN / 64, 256>>>(a);
    attn_mma_kernel<<<128, 256>>>(adj);
    finalize_kernel<<<1024, 256>>>(out);
}

// round 11
// speedup vs baseline: 4.6469x; 1.0984x over previous
#include <cuda_runtime.h>
#include <cuda_fp16.h>
#include <stdint.h>
#include <math.h>

#define NN 8192
#define INF_ 256
#define OUTF 128

// ------------------------------ scratch ------------------------------------
__device__ float g_Wh[NN * OUTF];          // 4 MB  row-major [j][c]
__device__ float g_R[NN];                  // exp(0.8*src)
__device__ float g_Q[NN];                  // exp(0.8*dst)
__device__ float g_D5[NN];                 // exp(0.2*dst)
__device__ float g_pnum[2 * NN * OUTF];    // 8 MB  split-K partial numerators
__device__ float g_pden[2 * NN];           // split-K partial denominators

// ------------------------------ helpers ------------------------------------
__device__ __forceinline__ uint32_t smem_u32(const void* p) {
    return (uint32_t)__cvta_generic_to_shared(p);
}
__device__ __forceinline__ void ldsm_x4(uint32_t* r, uint32_t addr) {
    asm volatile("ldmatrix.sync.aligned.m8n8.x4.shared.b16 {%0,%1,%2,%3}, [%4];"
        : "=r"(r[0]), "=r"(r[1]), "=r"(r[2]), "=r"(r[3]) : "r"(addr));
}
__device__ __forceinline__ void ldsm_x4_t(uint32_t* r, uint32_t addr) {
    asm volatile("ldmatrix.sync.aligned.m8n8.x4.trans.shared.b16 {%0,%1,%2,%3}, [%4];"
        : "=r"(r[0]), "=r"(r[1]), "=r"(r[2]), "=r"(r[3]) : "r"(addr));
}
// m16n8k16 f16 MMA, fp32 accumulate
__device__ __forceinline__ void mma_f16(float* d, const uint32_t* a, const uint32_t* b) {
    asm volatile(
        "mma.sync.aligned.m16n8k16.row.col.f32.f16.f16.f32 "
        "{%0,%1,%2,%3}, {%4,%5,%6,%7}, {%8,%9}, {%0,%1,%2,%3};"
        : "+f"(d[0]), "+f"(d[1]), "+f"(d[2]), "+f"(d[3])
        : "r"(a[0]), "r"(a[1]), "r"(a[2]), "r"(a[3]), "r"(b[0]), "r"(b[1]));
}
__device__ __forceinline__ uint32_t pack_h2(float lo, float hi) {
    __half2 h = __float22half2_rn(make_float2(lo, hi));
    return *(uint32_t*)&h;
}

// ---------------------------------------------------------------------------
// Kernel A: Wh = h @ W   (8192x256 @ 256x128), fp32
// ---------------------------------------------------------------------------
__global__ __launch_bounds__(256) void wh_kernel(const float* __restrict__ h,
                                                 const float* __restrict__ W) {
    __shared__ float hs[64 * 68];
    __shared__ float Ws[64 * 128];
    const int tid = threadIdx.x;
    const int ty = tid >> 4, tx = tid & 15;
    const int rowbase = blockIdx.x * 64;
    float acc[4][8];
#pragma unroll
    for (int i = 0; i < 4; i++)
#pragma unroll
        for (int c = 0; c < 8; c++) acc[i][c] = 0.f;
    const float4* h4 = (const float4*)h;
    const float4* W4 = (const float4*)W;
    for (int kt = 0; kt < INF_; kt += 64) {
        __syncthreads();
#pragma unroll
        for (int s = 0; s < 4; s++) {
            int f4 = tid + s * 256;
            int r = f4 >> 4, c4 = f4 & 15;
            float4 v = h4[(size_t)(rowbase + r) * 64 + (kt >> 2) + c4];
            *(float4*)&hs[r * 68 + c4 * 4] = v;
        }
#pragma unroll
        for (int s = 0; s < 8; s++) {
            int f4 = tid + s * 256;
            ((float4*)Ws)[f4] = W4[kt * 32 + f4];
        }
        __syncthreads();
#pragma unroll 8
        for (int k = 0; k < 64; k++) {
            float hv[4];
#pragma unroll
            for (int i = 0; i < 4; i++) hv[i] = hs[(ty * 4 + i) * 68 + k];
            float4 w0 = *(const float4*)&Ws[k * 128 + tx * 4];
            float4 w1 = *(const float4*)&Ws[k * 128 + 64 + tx * 4];
#pragma unroll
            for (int i = 0; i < 4; i++) {
                acc[i][0] += hv[i] * w0.x; acc[i][1] += hv[i] * w0.y;
                acc[i][2] += hv[i] * w0.z; acc[i][3] += hv[i] * w0.w;
                acc[i][4] += hv[i] * w1.x; acc[i][5] += hv[i] * w1.y;
                acc[i][6] += hv[i] * w1.z; acc[i][7] += hv[i] * w1.w;
            }
        }
    }
#pragma unroll
    for (int i = 0; i < 4; i++) {
        int r = rowbase + ty * 4 + i;
        ((float4*)g_Wh)[(size_t)r * 32 + tx] = make_float4(acc[i][0], acc[i][1], acc[i][2], acc[i][3]);
        ((float4*)g_Wh)[(size_t)r * 32 + 16 + tx] = make_float4(acc[i][4], acc[i][5], acc[i][6], acc[i][7]);
    }
}

// ---------------------------------------------------------------------------
// Kernel B: per-node R = exp(0.8*src), Q = exp(0.8*dst), D5 = exp(0.2*dst)
// ---------------------------------------------------------------------------
__global__ __launch_bounds__(256) void srcdst_kernel(const float* __restrict__ a) {
    const int tid = threadIdx.x;
    const int row = blockIdx.x * 64 + (tid >> 2);
    const int q = tid & 3;
    const float4* wh4 = (const float4*)(g_Wh + (size_t)row * 128) + q * 8;
    const float4* a4 = (const float4*)a;
    float s1 = 0.f, s2 = 0.f;
#pragma unroll
    for (int t = 0; t < 8; t++) {
        float4 v = wh4[t];
        float4 b1 = a4[q * 8 + t];
        float4 b2 = a4[32 + q * 8 + t];
        s1 += v.x * b1.x + v.y * b1.y + v.z * b1.z + v.w * b1.w;
        s2 += v.x * b2.x + v.y * b2.y + v.z * b2.z + v.w * b2.w;
    }
    s1 += __shfl_xor_sync(0xffffffffu, s1, 1);
    s1 += __shfl_xor_sync(0xffffffffu, s1, 2);
    s2 += __shfl_xor_sync(0xffffffffu, s2, 1);
    s2 += __shfl_xor_sync(0xffffffffu, s2, 2);
    if (q == 0) {
        g_R[row] = __expf(0.8f * s1);
        g_Q[row] = __expf(0.8f * s2);
        g_D5[row] = __expf(0.2f * s2);
    }
}

// ---------------------------------------------------------------------------
// Kernel C: fused masked-attention GEMM via f16 m16n8k16 + ldmatrix.
// grid = 128 (64 row-blocks x 2 K-halves), block = 512 (16 warps = 4m x 4n).
// CTA tile: 128 rows x 128 cols, j-tile = 64, double-buffered smem,
// ONE __syncthreads per tile.
// P_ij = adj ? max(R_i*Q_j, 1) : 0 (f16) ; B[j][c] = D5_j*Wh[j][c] (f16)
// num = P @ B (fp32 acc), den = sum_j P_ij*D5_j (fp32 scalar).
// ---------------------------------------------------------------------------
#define PST 72      // P smem row stride in halves (144 B) -> conflict-free
#define BST 136     // B smem row stride in halves (272 B) -> conflict-free
#define PS_BYTES (128 * PST * 2)    // 18432
#define BS_BYTES (64 * BST * 2)     // 17408
#define OFF_PS0 0
#define OFF_PS1 PS_BYTES
#define OFF_BS0 (2 * PS_BYTES)
#define OFF_BS1 (2 * PS_BYTES + BS_BYTES)
#define OFF_DEN (2 * PS_BYTES + 2 * BS_BYTES)
#define ATTN_SMEM (OFF_DEN + 128 * 8 * 4)   // 75776 B

__global__ __launch_bounds__(512, 1) void attn_mma_kernel(const int* __restrict__ adj) {
    extern __shared__ char sm[];
    float* Dens = (float*)(sm + OFF_DEN);

    const int tid = threadIdx.x;
    const int lane = tid & 31, wid = tid >> 5;
    const int rb = blockIdx.x >> 1, kh = blockIdx.x & 1;
    const int row0 = rb * 128, k0 = kh * 4096;

    // ---- P-build roles: thread covers rows {r0, r0+64} x j in [jq*8, jq*8+8) ----
    const int r0 = tid >> 3;            // 0..63
    const int jq = tid & 7;             // 0..7
    float Rr[2], den[2];
    const int4* adjp[2];
#pragma unroll
    for (int cc = 0; cc < 2; cc++) {
        Rr[cc] = g_R[row0 + r0 + 64 * cc];
        den[cc] = 0.f;
        adjp[cc] = (const int4*)(adj + (size_t)(row0 + r0 + 64 * cc) * NN + k0) + jq * 2;
    }

    // ---- MMA roles: 16 warps, wm = wid>>2 (rows wm*32), wn = wid&3 (cols wn*32) ----
    const int wm = wid >> 2, wn = wid & 3;
    const int gr = lane >> 2, tg = lane & 3;
    float acc[2][4][4];
#pragma unroll
    for (int mt = 0; mt < 2; mt++)
#pragma unroll
        for (int nt = 0; nt < 4; nt++)
#pragma unroll
            for (int i = 0; i < 4; i++) acc[mt][nt][i] = 0.f;

    const uint32_t ps_base = smem_u32(sm + OFF_PS0);
    const uint32_t bs_base = smem_u32(sm + OFF_BS0);
    // A: row = wm*32 + mt*16 + (lane&15), col = kk + (lane>>4)*8
    const uint32_t a_lane_off = (uint32_t)((wm * 32 + (lane & 15)) * PST + (lane >> 4) * 8) * 2;
    // B: row = kk + (lane&15), col = wn*32 + pr*16 + (lane>>4)*8
    const uint32_t b_lane_off = (uint32_t)((lane & 15) * BST + wn * 32 + (lane >> 4) * 8) * 2;

    // ---- prefetch tile 0 ----
    int4 av[2][2];
    float4 bv[4];
#pragma unroll
    for (int cc = 0; cc < 2; cc++) {
        av[cc][0] = adjp[cc][0];
        av[cc][1] = adjp[cc][1];
    }
#pragma unroll
    for (int s2 = 0; s2 < 4; s2++)
        bv[s2] = ((const float4*)g_Wh)[(size_t)(k0 + wid + 16 * s2) * 32 + lane];

    for (int s = 0; s < 64; s++) {
        const int b = s & 1;
        const int jbase = s * 64;
        __half* Ps = (__half*)(sm + (b ? OFF_PS1 : OFF_PS0));
        __half* Bs = (__half*)(sm + (b ? OFF_BS1 : OFF_BS0));

        // ---- stage P (f16) + den ----
        const float4 qv0 = __ldg((const float4*)(g_Q + k0 + jbase + jq * 8));
        const float4 qv1 = __ldg((const float4*)(g_Q + k0 + jbase + jq * 8 + 4));
        const float4 dv0 = __ldg((const float4*)(g_D5 + k0 + jbase + jq * 8));
        const float4 dv1 = __ldg((const float4*)(g_D5 + k0 + jbase + jq * 8 + 4));
#pragma unroll
        for (int cc = 0; cc < 2; cc++) {
            const int row = r0 + 64 * cc;
            const float R = Rr[cc];
            const int4 a0 = av[cc][0], a1 = av[cc][1];
            float p0 = a0.x ? fmaxf(R * qv0.x, 1.0f) : 0.0f;
            float p1 = a0.y ? fmaxf(R * qv0.y, 1.0f) : 0.0f;
            float p2 = a0.z ? fmaxf(R * qv0.z, 1.0f) : 0.0f;
            float p3 = a0.w ? fmaxf(R * qv0.w, 1.0f) : 0.0f;
            float p4 = a1.x ? fmaxf(R * qv1.x, 1.0f) : 0.0f;
            float p5 = a1.y ? fmaxf(R * qv1.y, 1.0f) : 0.0f;
            float p6 = a1.z ? fmaxf(R * qv1.z, 1.0f) : 0.0f;
            float p7 = a1.w ? fmaxf(R * qv1.w, 1.0f) : 0.0f;
            den[cc] += ((p0 * dv0.x + p1 * dv0.y) + (p2 * dv0.z + p3 * dv0.w)) +
                       ((p4 * dv1.x + p5 * dv1.y) + (p6 * dv1.z + p7 * dv1.w));
            uint4 u = make_uint4(pack_h2(p0, p1), pack_h2(p2, p3),
                                 pack_h2(p4, p5), pack_h2(p6, p7));
            *(uint4*)&Ps[row * PST + jq * 8] = u;
        }
        // ---- stage B (f16): j = wid + 16*s2, cols = lane*4 ----
#pragma unroll
        for (int s2 = 0; s2 < 4; s2++) {
            const int j = wid + 16 * s2;
            const float d5 = __ldg(g_D5 + k0 + jbase + j);
            float4 v = bv[s2];
            uint2 u = make_uint2(pack_h2(v.x * d5, v.y * d5), pack_h2(v.z * d5, v.w * d5));
            *(uint2*)&Bs[j * BST + lane * 4] = u;
        }

        // ---- prefetch next tile (issued before barrier; lands during MMA) ----
        if (s + 1 < 64) {
#pragma unroll
            for (int cc = 0; cc < 2; cc++) {
                av[cc][0] = adjp[cc][(s + 1) * 16];
                av[cc][1] = adjp[cc][(s + 1) * 16 + 1];
            }
#pragma unroll
            for (int s2 = 0; s2 < 4; s2++)
                bv[s2] = ((const float4*)g_Wh)[(size_t)(k0 + jbase + 64 + wid + 16 * s2) * 32 + lane];
        }
        __syncthreads();

        // ---- MMA: K=64 in 4 ksteps of 16 ----
        const uint32_t pbo = ps_base + (b ? PS_BYTES : 0) + a_lane_off;
        const uint32_t bbo = bs_base + (b ? BS_BYTES : 0) + b_lane_off;
#pragma unroll
        for (int k = 0; k < 4; k++) {
            const int kk = k * 16;
            uint32_t afr[2][4];
            ldsm_x4(afr[0], pbo + kk * 2);
            ldsm_x4(afr[1], pbo + (16 * PST + kk) * 2);
            uint32_t bfr[2][4];
#pragma unroll
            for (int pr = 0; pr < 2; pr++)
                ldsm_x4_t(bfr[pr], bbo + (kk * BST + pr * 16) * 2);
#pragma unroll
            for (int pr = 0; pr < 2; pr++) {
                mma_f16(acc[0][pr * 2], afr[0], &bfr[pr][0]);
                mma_f16(acc[1][pr * 2], afr[1], &bfr[pr][0]);
                mma_f16(acc[0][pr * 2 + 1], afr[0], &bfr[pr][2]);
                mma_f16(acc[1][pr * 2 + 1], afr[1], &bfr[pr][2]);
            }
        }
    }

    // ---- denominator reduce ----
    __syncthreads();
#pragma unroll
    for (int cc = 0; cc < 2; cc++) Dens[(r0 + 64 * cc) * 8 + jq] = den[cc];
    __syncthreads();
    if (tid < 128) {
        const float* dr = Dens + tid * 8;
        float sden = 0.f;
#pragma unroll
        for (int k = 0; k < 8; k++) sden += dr[k];
        g_pden[kh * NN + row0 + tid] = sden;
    }

    // ---- numerator writeback ----
    const size_t base = (size_t)kh * NN + row0;
#pragma unroll
    for (int mt = 0; mt < 2; mt++) {
        const int r_lo = wm * 32 + mt * 16 + gr;
#pragma unroll
        for (int nt = 0; nt < 4; nt++) {
            const int col = wn * 32 + nt * 8 + 2 * tg;
            *(float2*)&g_pnum[(base + r_lo) * 128 + col] = make_float2(acc[mt][nt][0], acc[mt][nt][1]);
            *(float2*)&g_pnum[(base + r_lo + 8) * 128 + col] = make_float2(acc[mt][nt][2], acc[mt][nt][3]);
        }
    }
}

// ---------------------------------------------------------------------------
// Kernel D: finalize  out = elu((n0+n1)/(d0+d1))
// ---------------------------------------------------------------------------
__global__ __launch_bounds__(256) void finalize_kernel(float* __restrict__ out) {
    const int idx = blockIdx.x * 256 + threadIdx.x;
    const int row = idx >> 5, c4 = idx & 31;
    float4 n0 = ((const float4*)g_pnum)[(size_t)row * 32 + c4];
    float4 n1 = ((const float4*)g_pnum)[(size_t)(NN + row) * 32 + c4];
    const float rinv = 1.0f / (g_pden[row] + g_pden[NN + row]);
    float4 o;
    float x;
    x = (n0.x + n1.x) * rinv; o.x = x > 0.f ? x : expm1f(x);
    x = (n0.y + n1.y) * rinv; o.y = x > 0.f ? x : expm1f(x);
    x = (n0.z + n1.z) * rinv; o.z = x > 0.f ? x : expm1f(x);
    x = (n0.w + n1.w) * rinv; o.w = x > 0.f ? x : expm1f(x);
    ((float4*)out)[(size_t)row * 32 + c4] = o;
}

// ---------------------------------------------------------------------------
extern "C" void kernel_launch(void* const* d_in, const int* in_sizes, int n_in,
                              void* d_out, int out_size) {
    const float* h = (const float*)d_in[0];
    const int* adj = (const int*)d_in[1];
    const float* W = (const float*)d_in[2];
    const float* a = (const float*)d_in[3];
    float* out = (float*)d_out;

    cudaFuncSetAttribute(attn_mma_kernel, cudaFuncAttributeMaxDynamicSharedMemorySize,
                         ATTN_SMEM);

    wh_kernel<<<NN / 64, 256>>>(h, W);
    srcdst_kernel<<<NN / 64, 256>>>(a);
    attn_mma_kernel<<<128, 512, ATTN_SMEM>>>(adj);
    finalize_kernel<<<1024, 256>>>(out);
}

// round 12
// speedup vs baseline: 5.3959x; 1.1612x over previous
#include <cuda_runtime.h>
#include <cuda_fp16.h>
#include <stdint.h>
#include <math.h>

#define NN 8192
#define INF_ 256
#define OUTF 128

// ------------------------------ scratch ------------------------------------
__device__ float g_Wh[NN * OUTF];          // 4 MB  row-major [j][c]
__device__ __half g_Bh[NN * OUTF];         // 2 MB  f16 B = D5_j * Wh[j][c]
__device__ float g_R[NN];                  // exp(0.8*src)
__device__ float g_Q[NN];                  // exp(0.8*dst)
__device__ float g_D5[NN];                 // exp(0.2*dst)
__device__ float g_pnum[2 * NN * OUTF];    // 8 MB  split-K partial numerators
__device__ float g_pden[2 * NN];           // split-K partial denominators

// ------------------------------ helpers ------------------------------------
__device__ __forceinline__ uint32_t smem_u32(const void* p) {
    return (uint32_t)__cvta_generic_to_shared(p);
}
__device__ __forceinline__ void ldsm_x4(uint32_t* r, uint32_t addr) {
    asm volatile("ldmatrix.sync.aligned.m8n8.x4.shared.b16 {%0,%1,%2,%3}, [%4];"
        : "=r"(r[0]), "=r"(r[1]), "=r"(r[2]), "=r"(r[3]) : "r"(addr));
}
__device__ __forceinline__ void ldsm_x4_t(uint32_t* r, uint32_t addr) {
    asm volatile("ldmatrix.sync.aligned.m8n8.x4.trans.shared.b16 {%0,%1,%2,%3}, [%4];"
        : "=r"(r[0]), "=r"(r[1]), "=r"(r[2]), "=r"(r[3]) : "r"(addr));
}
__device__ __forceinline__ void mma_f16(float* d, const uint32_t* a, const uint32_t* b) {
    asm volatile(
        "mma.sync.aligned.m16n8k16.row.col.f32.f16.f16.f32 "
        "{%0,%1,%2,%3}, {%4,%5,%6,%7}, {%8,%9}, {%0,%1,%2,%3};"
        : "+f"(d[0]), "+f"(d[1]), "+f"(d[2]), "+f"(d[3])
        : "r"(a[0]), "r"(a[1]), "r"(a[2]), "r"(a[3]), "r"(b[0]), "r"(b[1]));
}
__device__ __forceinline__ uint32_t pack_h2(float lo, float hi) {
    __half2 h = __float22half2_rn(make_float2(lo, hi));
    return *(uint32_t*)&h;
}
__device__ __forceinline__ void cp_async16(uint32_t dst, const void* src) {
    asm volatile("cp.async.cg.shared.global [%0], [%1], 16;" :: "r"(dst), "l"(src));
}
#define CP_COMMIT()  asm volatile("cp.async.commit_group;" ::: "memory")
#define CP_WAIT0()   asm volatile("cp.async.wait_group 0;" ::: "memory")

// ---------------------------------------------------------------------------
// Kernel A: Wh = h @ W   (8192x256 @ 256x128), fp32
// ---------------------------------------------------------------------------
__global__ __launch_bounds__(256) void wh_kernel(const float* __restrict__ h,
                                                 const float* __restrict__ W) {
    __shared__ float hs[64 * 68];
    __shared__ float Ws[64 * 128];
    const int tid = threadIdx.x;
    const int ty = tid >> 4, tx = tid & 15;
    const int rowbase = blockIdx.x * 64;
    float acc[4][8];
#pragma unroll
    for (int i = 0; i < 4; i++)
#pragma unroll
        for (int c = 0; c < 8; c++) acc[i][c] = 0.f;
    const float4* h4 = (const float4*)h;
    const float4* W4 = (const float4*)W;
    for (int kt = 0; kt < INF_; kt += 64) {
        __syncthreads();
#pragma unroll
        for (int s = 0; s < 4; s++) {
            int f4 = tid + s * 256;
            int r = f4 >> 4, c4 = f4 & 15;
            float4 v = h4[(size_t)(rowbase + r) * 64 + (kt >> 2) + c4];
            *(float4*)&hs[r * 68 + c4 * 4] = v;
        }
#pragma unroll
        for (int s = 0; s < 8; s++) {
            int f4 = tid + s * 256;
            ((float4*)Ws)[f4] = W4[kt * 32 + f4];
        }
        __syncthreads();
#pragma unroll 8
        for (int k = 0; k < 64; k++) {
            float hv[4];
#pragma unroll
            for (int i = 0; i < 4; i++) hv[i] = hs[(ty * 4 + i) * 68 + k];
            float4 w0 = *(const float4*)&Ws[k * 128 + tx * 4];
            float4 w1 = *(const float4*)&Ws[k * 128 + 64 + tx * 4];
#pragma unroll
            for (int i = 0; i < 4; i++) {
                acc[i][0] += hv[i] * w0.x; acc[i][1] += hv[i] * w0.y;
                acc[i][2] += hv[i] * w0.z; acc[i][3] += hv[i] * w0.w;
                acc[i][4] += hv[i] * w1.x; acc[i][5] += hv[i] * w1.y;
                acc[i][6] += hv[i] * w1.z; acc[i][7] += hv[i] * w1.w;
            }
        }
    }
#pragma unroll
    for (int i = 0; i < 4; i++) {
        int r = rowbase + ty * 4 + i;
        ((float4*)g_Wh)[(size_t)r * 32 + tx] = make_float4(acc[i][0], acc[i][1], acc[i][2], acc[i][3]);
        ((float4*)g_Wh)[(size_t)r * 32 + 16 + tx] = make_float4(acc[i][4], acc[i][5], acc[i][6], acc[i][7]);
    }
}

// ---------------------------------------------------------------------------
// Kernel B: per-node R = exp(0.8*src), Q = exp(0.8*dst), D5 = exp(0.2*dst)
// ---------------------------------------------------------------------------
__global__ __launch_bounds__(256) void srcdst_kernel(const float* __restrict__ a) {
    const int tid = threadIdx.x;
    const int row = blockIdx.x * 64 + (tid >> 2);
    const int q = tid & 3;
    const float4* wh4 = (const float4*)(g_Wh + (size_t)row * 128) + q * 8;
    const float4* a4 = (const float4*)a;
    float s1 = 0.f, s2 = 0.f;
#pragma unroll
    for (int t = 0; t < 8; t++) {
        float4 v = wh4[t];
        float4 b1 = a4[q * 8 + t];
        float4 b2 = a4[32 + q * 8 + t];
        s1 += v.x * b1.x + v.y * b1.y + v.z * b1.z + v.w * b1.w;
        s2 += v.x * b2.x + v.y * b2.y + v.z * b2.z + v.w * b2.w;
    }
    s1 += __shfl_xor_sync(0xffffffffu, s1, 1);
    s1 += __shfl_xor_sync(0xffffffffu, s1, 2);
    s2 += __shfl_xor_sync(0xffffffffu, s2, 1);
    s2 += __shfl_xor_sync(0xffffffffu, s2, 2);
    if (q == 0) {
        g_R[row] = __expf(0.8f * s1);
        g_Q[row] = __expf(0.8f * s2);
        g_D5[row] = __expf(0.2f * s2);
    }
}

// ---------------------------------------------------------------------------
// Kernel B2: Bh[j][c] = f16(D5_j * Wh[j][c])
// ---------------------------------------------------------------------------
__global__ __launch_bounds__(256) void bh_kernel() {
    const int idx = blockIdx.x * 256 + threadIdx.x;   // 0..262143
    const int row = idx >> 5, c4 = idx & 31;
    const float d5 = g_D5[row];
    float4 v = ((const float4*)g_Wh)[(size_t)row * 32 + c4];
    uint2 u = make_uint2(pack_h2(v.x * d5, v.y * d5), pack_h2(v.z * d5, v.w * d5));
    *(uint2*)&g_Bh[(size_t)row * 128 + c4 * 4] = u;
}

// ---------------------------------------------------------------------------
// Kernel C: fused masked-attention GEMM via f16 m16n8k16 + ldmatrix.
// grid = 256 (128 row-blocks of 64 x 2 K-halves), block = 256 (8 warps),
// 2 CTAs/SM. CTA tile: 64 rows x 128 cols, j-tile = 64, double-buffered,
// B tiles via cp.async from precomputed f16 g_Bh.
// ---------------------------------------------------------------------------
#define PST 72      // P smem row stride in halves (144 B) -> conflict-free
#define BST 136     // B smem row stride in halves (272 B) -> conflict-free
#define PS_B (64 * PST * 2)     //  9216 B per buffer
#define BS_B (64 * BST * 2)     // 17408 B per buffer
#define OFF_PS0 0
#define OFF_PS1 PS_B
#define OFF_BS0 (2 * PS_B)
#define OFF_BS1 (2 * PS_B + BS_B)
#define OFF_DEN (2 * PS_B + 2 * BS_B)
#define ATTN_SMEM (OFF_DEN + 64 * 8 * 4)    // 55296 B

__global__ __launch_bounds__(256, 2) void attn_mma_kernel(const int* __restrict__ adj) {
    extern __shared__ char sm[];
    float* Dens = (float*)(sm + OFF_DEN);

    const int tid = threadIdx.x;
    const int lane = tid & 31, wid = tid >> 5;
    const int rb = blockIdx.x >> 1, kh = blockIdx.x & 1;
    const int row0 = rb * 64, k0 = kh * 4096;

    // ---- P-build roles: rows {r0, r0+32}, j in [jq*8, jq*8+8) ----
    const int r0 = tid >> 3;            // 0..31
    const int jq = tid & 7;             // 0..7
    float Rr[2], den[2];
    const int4* adjp[2];
#pragma unroll
    for (int cc = 0; cc < 2; cc++) {
        Rr[cc] = g_R[row0 + r0 + 32 * cc];
        den[cc] = 0.f;
        adjp[cc] = (const int4*)(adj + (size_t)(row0 + r0 + 32 * cc) * NN + k0) + jq * 2;
    }

    // ---- MMA roles: 8 warps = 4m (16 rows) x 2n (64 cols) ----
    const int wm = wid >> 1, wn = wid & 1;
    const int gr = lane >> 2, tg = lane & 3;
    float acc[8][4];
#pragma unroll
    for (int nt = 0; nt < 8; nt++)
#pragma unroll
        for (int i = 0; i < 4; i++) acc[nt][i] = 0.f;

    const uint32_t ps_base = smem_u32(sm);
    const uint32_t a_lane_off = ps_base + (uint32_t)((wm * 16 + (lane & 15)) * PST + (lane >> 4) * 8) * 2;
    const uint32_t b_lane_off = ps_base + OFF_BS0 + (uint32_t)((lane & 15) * BST + wn * 64 + (lane >> 4) * 8) * 2;

    // ---- B cp.async tasks: 4 per thread; task = tid + 256*i -> (j, 16B chunk) ----
    // dst halves offset: j*BST + ch*8 ; src: g_Bh[(k0+jbase+j)*128 + ch*8]
    const int bj0 = tid >> 4;           // j for task i via  j = bj0 + 16*i  (tid%16 = ch)
    const int bch = tid & 15;

    // ---- preamble: cp.async B(0), av(0), Q/D5(0) ----
    {
        const uint32_t dst = ps_base + OFF_BS0;
#pragma unroll
        for (int i = 0; i < 4; i++) {
            const int j = bj0 + 16 * i;
            cp_async16(dst + (uint32_t)(j * BST + bch * 8) * 2,
                       g_Bh + (size_t)(k0 + j) * 128 + bch * 8);
        }
        CP_COMMIT();
    }
    int4 av[2][2];
#pragma unroll
    for (int cc = 0; cc < 2; cc++) { av[cc][0] = adjp[cc][0]; av[cc][1] = adjp[cc][1]; }
    float4 qv0 = __ldg((const float4*)(g_Q + k0 + jq * 8));
    float4 qv1 = __ldg((const float4*)(g_Q + k0 + jq * 8 + 4));
    float4 dv0 = __ldg((const float4*)(g_D5 + k0 + jq * 8));
    float4 dv1 = __ldg((const float4*)(g_D5 + k0 + jq * 8 + 4));

    for (int s = 0; s < 64; s++) {
        const int b = s & 1;
        __half* Ps = (__half*)(sm + (b ? OFF_PS1 : OFF_PS0));

        // ---- build P(s) (f16) + den ----
#pragma unroll
        for (int cc = 0; cc < 2; cc++) {
            const int row = r0 + 32 * cc;
            const float R = Rr[cc];
            const int4 a0 = av[cc][0], a1 = av[cc][1];
            float p0 = a0.x ? fmaxf(R * qv0.x, 1.0f) : 0.0f;
            float p1 = a0.y ? fmaxf(R * qv0.y, 1.0f) : 0.0f;
            float p2 = a0.z ? fmaxf(R * qv0.z, 1.0f) : 0.0f;
            float p3 = a0.w ? fmaxf(R * qv0.w, 1.0f) : 0.0f;
            float p4 = a1.x ? fmaxf(R * qv1.x, 1.0f) : 0.0f;
            float p5 = a1.y ? fmaxf(R * qv1.y, 1.0f) : 0.0f;
            float p6 = a1.z ? fmaxf(R * qv1.z, 1.0f) : 0.0f;
            float p7 = a1.w ? fmaxf(R * qv1.w, 1.0f) : 0.0f;
            den[cc] += ((p0 * dv0.x + p1 * dv0.y) + (p2 * dv0.z + p3 * dv0.w)) +
                       ((p4 * dv1.x + p5 * dv1.y) + (p6 * dv1.z + p7 * dv1.w));
            uint4 u = make_uint4(pack_h2(p0, p1), pack_h2(p2, p3),
                                 pack_h2(p4, p5), pack_h2(p6, p7));
            *(uint4*)&Ps[row * PST + jq * 8] = u;
        }

        // ---- prefetch av / Q / D5 for tile s+1 (fly during MMA) ----
        if (s + 1 < 64) {
            const int jb1 = (s + 1) * 64;
#pragma unroll
            for (int cc = 0; cc < 2; cc++) {
                av[cc][0] = adjp[cc][(s + 1) * 16];
                av[cc][1] = adjp[cc][(s + 1) * 16 + 1];
            }
            qv0 = __ldg((const float4*)(g_Q + k0 + jb1 + jq * 8));
            qv1 = __ldg((const float4*)(g_Q + k0 + jb1 + jq * 8 + 4));
            dv0 = __ldg((const float4*)(g_D5 + k0 + jb1 + jq * 8));
            dv1 = __ldg((const float4*)(g_D5 + k0 + jb1 + jq * 8 + 4));
        }

        CP_WAIT0();            // B(s) landed
        __syncthreads();       // P(s) + B(s) visible; buffers b^1 free

        // ---- issue cp.async for B(s+1) into buffer b^1 ----
        if (s + 1 < 64) {
            const uint32_t dst = ps_base + (b ? OFF_BS0 : OFF_BS1);
            const int jb1 = (s + 1) * 64;
#pragma unroll
            for (int i = 0; i < 4; i++) {
                const int j = bj0 + 16 * i;
                cp_async16(dst + (uint32_t)(j * BST + bch * 8) * 2,
                           g_Bh + (size_t)(k0 + jb1 + j) * 128 + bch * 8);
            }
            CP_COMMIT();
        }

        // ---- MMA(s): K=64 in 4 ksteps of 16 ----
        const uint32_t pbo = a_lane_off + (b ? PS_B : 0);
        const uint32_t bbo = b_lane_off + (b ? BS_B : 0);
#pragma unroll
        for (int k = 0; k < 4; k++) {
            const int kk = k * 16;
            uint32_t afr[4];
            ldsm_x4(afr, pbo + kk * 2);
            uint32_t bfr[4][4];
#pragma unroll
            for (int pr = 0; pr < 4; pr++)
                ldsm_x4_t(bfr[pr], bbo + (kk * BST + pr * 16) * 2);
#pragma unroll
            for (int pr = 0; pr < 4; pr++) {
                mma_f16(acc[pr * 2], afr, &bfr[pr][0]);
                mma_f16(acc[pr * 2 + 1], afr, &bfr[pr][2]);
            }
        }
    }

    // ---- denominator reduce ----
    __syncthreads();
#pragma unroll
    for (int cc = 0; cc < 2; cc++) Dens[(r0 + 32 * cc) * 8 + jq] = den[cc];
    __syncthreads();
    if (tid < 64) {
        const float* dr = Dens + tid * 8;
        float sden = 0.f;
#pragma unroll
        for (int k = 0; k < 8; k++) sden += dr[k];
        g_pden[kh * NN + row0 + tid] = sden;
    }

    // ---- numerator writeback ----
    const size_t base = (size_t)kh * NN + row0;
    const int r_lo = wm * 16 + gr;
#pragma unroll
    for (int nt = 0; nt < 8; nt++) {
        const int col = wn * 64 + nt * 8 + 2 * tg;
        *(float2*)&g_pnum[(base + r_lo) * 128 + col] = make_float2(acc[nt][0], acc[nt][1]);
        *(float2*)&g_pnum[(base + r_lo + 8) * 128 + col] = make_float2(acc[nt][2], acc[nt][3]);
    }
}

// ---------------------------------------------------------------------------
// Kernel D: finalize  out = elu((n0+n1)/(d0+d1))
// ---------------------------------------------------------------------------
__global__ __launch_bounds__(256) void finalize_kernel(float* __restrict__ out) {
    const int idx = blockIdx.x * 256 + threadIdx.x;
    const int row = idx >> 5, c4 = idx & 31;
    float4 n0 = ((const float4*)g_pnum)[(size_t)row * 32 + c4];
    float4 n1 = ((const float4*)g_pnum)[(size_t)(NN + row) * 32 + c4];
    const float rinv = 1.0f / (g_pden[row] + g_pden[NN + row]);
    float4 o;
    float x;
    x = (n0.x + n1.x) * rinv; o.x = x > 0.f ? x : expm1f(x);
    x = (n0.y + n1.y) * rinv; o.y = x > 0.f ? x : expm1f(x);
    x = (n0.z + n1.z) * rinv; o.z = x > 0.f ? x : expm1f(x);
    x = (n0.w + n1.w) * rinv; o.w = x > 0.f ? x : expm1f(x);
    ((float4*)out)[(size_t)row * 32 + c4] = o;
}

// ---------------------------------------------------------------------------
extern "C" void kernel_launch(void* const* d_in, const int* in_sizes, int n_in,
                              void* d_out, int out_size) {
    const float* h = (const float*)d_in[0];
    const int* adj = (const int*)d_in[1];
    const float* W = (const float*)d_in[2];
    const float* a = (const float*)d_in[3];
    float* out = (float*)d_out;

    cudaFuncSetAttribute(attn_mma_kernel, cudaFuncAttributeMaxDynamicSharedMemorySize,
                         ATTN_SMEM);

    wh_kernel<<<NN / 64, 256>>>(h, W);
    srcdst_kernel<<<NN / 64, 256>>>(a);
    bh_kernel<<<NN * 32 / 256, 256>>>();
    attn_mma_kernel<<<256, 256, ATTN_SMEM>>>(adj);
    finalize_kernel<<<1024, 256>>>(out);
}